// round 12
// baseline (speedup 1.0000x reference)
#include <cuda_runtime.h>
#include <cstdint>

#define IN_DIM   16
#define OUT_DIM  32
#define TPB      256
#define WARPS    8
#define RPB      128            // rows per block-tile (16 rows per warp)
#define C15      286331154u     // ceil(2^32/15) (safe-path rounding)
#define FMAGIC   0x4B400000     // 12582912.0f = 1.5 * 2^23

__global__ void __launch_bounds__(TPB, 5)
quant_fused_kernel(const float4* __restrict__ in, float4* __restrict__ out,
                   const float* __restrict__ weight,
                   const float* __restrict__ pInMin,
                   const float* __restrict__ pInMax,
                   int rows, int numTiles) {
    __shared__ __align__(16) uint32_t s_q[WARPS][64];   // 16 rows x 4 packed q chunks
    __shared__ __align__(16) uint32_t s_K[WARPS][64];   // 16 rows x 4 K-words
    __shared__ uint32_t s_ab[WARPS][16];   // per-row: 4 bytes a_c (floor(T_c/15))
    __shared__ uint4    s_wp[OUT_DIM];
    __shared__ uint4    s_wm[OUT_DIM];
    __shared__ float4   s_bias[OUT_DIM / 4];
    __shared__ int      s_hz;

    const int tid = threadIdx.x;
    const int w = tid >> 5, t = tid & 31;

    const float InMin = *pInMin, InMax = *pInMax;
    const float scale = InMax - InMin;
    const float qa = 15.0f / scale;
    const float qb = -InMin * 15.0f / scale;
    const float scale4 = scale * 0.25f;     // exact (power-of-2 scaling)

    // ---- fused prep (warp 0): pack sign masks, bias, zero-flag ----
    if (tid < 32) {
        int o = tid;
        int anyz = 0, ssum = 0;
        uint32_t wp[4], wm[4];
        #pragma unroll
        for (int c = 0; c < 4; c++) {
            uint32_t p = 0, m = 0;
            #pragma unroll
            for (int j = 0; j < 4; j++) {
                float wv = weight[o * IN_DIM + c * 4 + j];
                int s = (wv > 0.0f) ? 1 : ((wv < 0.0f) ? -1 : 0);
                ssum += s;
                anyz |= (s == 0);
                if (s > 0) p |= 1u << (8 * j);
                if (s < 0) m |= 1u << (8 * j);
            }
            wp[c] = p; wm[c] = m;
        }
        s_wp[o] = make_uint4(wp[0], wp[1], wp[2], wp[3]);
        s_wm[o] = make_uint4(wm[0], wm[1], wm[2], wm[3]);
        ((float*)s_bias)[o] = InMin * (float)ssum;
        unsigned zb = __ballot_sync(0xffffffffu, anyz);
        if (o == 0) s_hz = (zb != 0u) ? 1 : 0;
    }
    __syncthreads();

    const int g  = t >> 3;          // row offset within group-of-4
    const int oq = t & 7;           // output float4 owned by this thread
    const float4 bias = s_bias[oq];

    // float-magic epilogue: __int_as_float(FMAGIC + tot4) = 12582912 + tot4
    const float mc = 12582912.0f * scale4;
    const float4 biasM = make_float4(bias.x - mc, bias.y - mc, bias.z - mc, bias.w - mc);

    const uint4 w0 = s_wp[oq * 4 + 0];
    const uint4 w1 = s_wp[oq * 4 + 1];
    const uint4 w2 = s_wp[oq * 4 + 2];
    const uint4 w3 = s_wp[oq * 4 + 3];

    if (!s_hz) {
        // ================= HOT PATH (no zero-sign weights) =================
        for (int tile = blockIdx.x; tile < numTiles; tile += gridDim.x) {
            int tileRow = tile * RPB + w * 16;

            const float4* ip = in + (size_t)tileRow * 4;
            #pragma unroll
            for (int i = 0; i < 2; i++) {
                int n = i * 32 + t;                    // = rlocal*4 + chunk (rows 0..15)
                float4 x = make_float4(0.f, 0.f, 0.f, 0.f);
                if (tileRow + (n >> 2) < rows) x = ip[n];
                int e0 = __float2int_rn(fmaf(x.x, qa, qb));
                int e1 = __float2int_rn(fmaf(x.y, qa, qb));
                int e2 = __float2int_rn(fmaf(x.z, qa, qb));
                int e3 = __float2int_rn(fmaf(x.w, qa, qb));
                uint32_t qw = __byte_perm(__byte_perm(e0, e1, 0x0040),
                                          __byte_perm(e2, e3, 0x0040), 0x5410);
                s_q[w][n] = qw;
                unsigned T = __dp4a(qw, 0x01010101u, 14u);   // S_c + 14, <= 74
                unsigned a = (69u * T) >> 10;                // floor(T/15)
                unsigned b = T - 15u * a;                    // [0,14]
                s_K[w][n] = (966u - 69u * b) << 16;          // 966 = 69*14
                ((uint8_t*)s_ab[w])[n] = (uint8_t)a;         // byte per chunk
            }
            __syncwarp();

            float4* op = out + (size_t)tileRow * 8;
            #pragma unroll 1
            for (int j = 0; j < 4; j++) {
                int r = 4 * j + g;
                uint4 q = ((const uint4*)s_q[w])[r];
                uint4 K = ((const uint4*)s_K[w])[r];
                int seed = __dp4a((int)s_ab[w][r], (int)0xFCFCFCFC, FMAGIC);
                float4 ov;
                unsigned acc;
                // v = (yP+7)*0x450045 + K; fields at bits 10-14 / 26-30 are
                // carry-free; bytes 1/3 of acc = Lo<<2 / Hi<<2; final dp4a =
                // FMAGIC + 4*tot -> reinterpret float = 12582912 + 4*tot (exact).
                acc  = (__dp4a(q.x, w0.x, 7u) * 0x00450045u + K.x) & 0x1C001C00u;
                acc += (__dp4a(q.y, w0.y, 7u) * 0x00450045u + K.y) & 0x1C001C00u;
                acc += (__dp4a(q.z, w0.z, 7u) * 0x00450045u + K.z) & 0x1C001C00u;
                acc += (__dp4a(q.w, w0.w, 7u) * 0x00450045u + K.w) & 0x1C001C00u;
                ov.x = fmaf(__int_as_float(__dp4a((int)acc, 0x01000100, seed)), scale4, biasM.x);
                acc  = (__dp4a(q.x, w1.x, 7u) * 0x00450045u + K.x) & 0x1C001C00u;
                acc += (__dp4a(q.y, w1.y, 7u) * 0x00450045u + K.y) & 0x1C001C00u;
                acc += (__dp4a(q.z, w1.z, 7u) * 0x00450045u + K.z) & 0x1C001C00u;
                acc += (__dp4a(q.w, w1.w, 7u) * 0x00450045u + K.w) & 0x1C001C00u;
                ov.y = fmaf(__int_as_float(__dp4a((int)acc, 0x01000100, seed)), scale4, biasM.y);
                acc  = (__dp4a(q.x, w2.x, 7u) * 0x00450045u + K.x) & 0x1C001C00u;
                acc += (__dp4a(q.y, w2.y, 7u) * 0x00450045u + K.y) & 0x1C001C00u;
                acc += (__dp4a(q.z, w2.z, 7u) * 0x00450045u + K.z) & 0x1C001C00u;
                acc += (__dp4a(q.w, w2.w, 7u) * 0x00450045u + K.w) & 0x1C001C00u;
                ov.z = fmaf(__int_as_float(__dp4a((int)acc, 0x01000100, seed)), scale4, biasM.z);
                acc  = (__dp4a(q.x, w3.x, 7u) * 0x00450045u + K.x) & 0x1C001C00u;
                acc += (__dp4a(q.y, w3.y, 7u) * 0x00450045u + K.y) & 0x1C001C00u;
                acc += (__dp4a(q.z, w3.z, 7u) * 0x00450045u + K.z) & 0x1C001C00u;
                acc += (__dp4a(q.w, w3.w, 7u) * 0x00450045u + K.w) & 0x1C001C00u;
                ov.w = fmaf(__int_as_float(__dp4a((int)acc, 0x01000100, seed)), scale4, biasM.w);
                if (tileRow + r < rows) op[(size_t)r * 8 + oq] = ov;
            }
            __syncwarp();
        }
    } else {
        // ================= SAFE PATH (some sign(w)==0) =================
        for (int tile = blockIdx.x; tile < numTiles; tile += gridDim.x) {
            int tileRow = tile * RPB + w * 16;

            const float4* ip = in + (size_t)tileRow * 4;
            #pragma unroll
            for (int i = 0; i < 2; i++) {
                int n = i * 32 + t;
                float4 x = make_float4(0.f, 0.f, 0.f, 0.f);
                if (tileRow + (n >> 2) < rows) x = ip[n];
                int e0 = __float2int_rn(fmaf(x.x, qa, qb));
                int e1 = __float2int_rn(fmaf(x.y, qa, qb));
                int e2 = __float2int_rn(fmaf(x.z, qa, qb));
                int e3 = __float2int_rn(fmaf(x.w, qa, qb));
                s_q[w][n] = __byte_perm(__byte_perm(e0, e1, 0x0040),
                                        __byte_perm(e2, e3, 0x0040), 0x5410);
            }
            __syncwarp();

            float4* op = out + (size_t)tileRow * 8;
            #pragma unroll 1
            for (int j = 0; j < 4; j++) {
                int r = 4 * j + g;
                uint4 q = ((const uint4*)s_q[w])[r];
                float4 ov;
                float* ovp = (float*)&ov;
                #pragma unroll
                for (int oi = 0; oi < 4; oi++) {
                    uint4 wp = s_wp[oq * 4 + oi];
                    uint4 wm = s_wm[oq * 4 + oi];
                    unsigned rp0 = __dp4a(q.x, wp.x, 7u), rm0 = __dp4a(q.x, wm.x, 7u);
                    unsigned rp1 = __dp4a(q.y, wp.y, 7u), rm1 = __dp4a(q.y, wm.y, 7u);
                    unsigned rp2 = __dp4a(q.z, wp.z, 7u), rm2 = __dp4a(q.z, wm.z, 7u);
                    unsigned rp3 = __dp4a(q.w, wp.w, 7u), rm3 = __dp4a(q.w, wm.w, 7u);
                    int acc = (int)__umulhi(rp0, C15) - (int)__umulhi(rm0, C15)
                            + (int)__umulhi(rp1, C15) - (int)__umulhi(rm1, C15)
                            + (int)__umulhi(rp2, C15) - (int)__umulhi(rm2, C15)
                            + (int)__umulhi(rp3, C15) - (int)__umulhi(rm3, C15);
                    ovp[oi] = fmaf((float)acc, scale, ((const float*)&bias)[oi]);
                }
                if (tileRow + r < rows) op[(size_t)r * 8 + oq] = ov;
            }
            __syncwarp();
        }
    }
}

extern "C" void kernel_launch(void* const* d_in, const int* in_sizes, int n_in,
                              void* d_out, int out_size) {
    const float* Input  = (const float*)d_in[0];
    const float* weight = (const float*)d_in[1];
    const float* InMin  = (const float*)d_in[2];
    const float* InMax  = (const float*)d_in[3];
    float* out = (float*)d_out;

    int rows = in_sizes[0] / IN_DIM;
    int numTiles = (rows + RPB - 1) / RPB;

    int blocks = 148 * 5;                  // one resident wave at 5 CTAs/SM
    if (blocks > numTiles) blocks = numTiles;

    quant_fused_kernel<<<blocks, TPB>>>((const float4*)Input, (float4*)out,
                                        weight, InMin, InMax, rows, numTiles);
}

// round 13
// speedup vs baseline: 1.1572x; 1.1572x over previous
#include <cuda_runtime.h>
#include <cstdint>

#define IN_DIM   16
#define OUT_DIM  32
#define TPB      256
#define WARPS    8
#define RPB      256            // rows per block-tile
#define C15      286331154u     // ceil(2^32/15) (safe-path rounding)
#define FMAGIC   0x4B400000     // 12582912.0f = 1.5 * 2^23

__global__ void __launch_bounds__(TPB, 4)
quant_fused_kernel(const float4* __restrict__ in, float4* __restrict__ out,
                   const float* __restrict__ weight,
                   const float* __restrict__ pInMin,
                   const float* __restrict__ pInMax,
                   int rows, int numTiles) {
    __shared__ __align__(16) uint32_t s_q[WARPS][128];  // 32 rows x 4 packed q chunks
    __shared__ __align__(16) uint32_t s_K[WARPS][128];  // 32 rows x 4 K-words 69*(74-T)<<16
    __shared__ uint4    s_wp[OUT_DIM];
    __shared__ uint4    s_wm[OUT_DIM];
    __shared__ float4   s_bias[OUT_DIM / 4];
    __shared__ int      s_hz;

    const int tid = threadIdx.x;
    const int w = tid >> 5, t = tid & 31;

    const float InMin = *pInMin, InMax = *pInMax;
    const float scale = InMax - InMin;
    const float qa = 15.0f / scale;
    const float qb = -InMin * 15.0f / scale;
    const float scale4 = scale * 0.25f;     // exact (power-of-2 scaling)

    // ---- fused prep (warp 0): pack sign masks, bias, zero-flag ----
    if (tid < 32) {
        int o = tid;
        int anyz = 0, ssum = 0;
        uint32_t wp[4], wm[4];
        #pragma unroll
        for (int c = 0; c < 4; c++) {
            uint32_t p = 0, m = 0;
            #pragma unroll
            for (int j = 0; j < 4; j++) {
                float wv = weight[o * IN_DIM + c * 4 + j];
                int s = (wv > 0.0f) ? 1 : ((wv < 0.0f) ? -1 : 0);
                ssum += s;
                anyz |= (s == 0);
                if (s > 0) p |= 1u << (8 * j);
                if (s < 0) m |= 1u << (8 * j);
            }
            wp[c] = p; wm[c] = m;
        }
        s_wp[o] = make_uint4(wp[0], wp[1], wp[2], wp[3]);
        s_wm[o] = make_uint4(wm[0], wm[1], wm[2], wm[3]);
        ((float*)s_bias)[o] = InMin * (float)ssum;
        unsigned zb = __ballot_sync(0xffffffffu, anyz);
        if (o == 0) s_hz = (zb != 0u) ? 1 : 0;
    }
    __syncthreads();

    const int g  = t >> 3;          // row offset within group-of-4
    const int oq = t & 7;           // output float4 owned by this thread
    const float4 bias = s_bias[oq];

    // float-magic epilogue: __int_as_float(FMAGIC + tot4) = 12582912 + tot4.
    // term_c = floor(x/15) + floor((x+74-T_c)/15) - 4  (constant -4 per chunk!)
    // => tot4 = 4*(SumLo + SumHi) - 64, so seed is the loop-invariant constant:
    const int seedC = (int)(FMAGIC - 64);
    const float mc = 12582912.0f * scale4;
    const float4 biasM = make_float4(bias.x - mc, bias.y - mc, bias.z - mc, bias.w - mc);

    const uint4 w0 = s_wp[oq * 4 + 0];
    const uint4 w1 = s_wp[oq * 4 + 1];
    const uint4 w2 = s_wp[oq * 4 + 2];
    const uint4 w3 = s_wp[oq * 4 + 3];

    if (!s_hz) {
        // ================= HOT PATH (no zero-sign weights) =================
        for (int tile = blockIdx.x; tile < numTiles; tile += gridDim.x) {
            int tileRow = tile * RPB + w * 32;

            const float4* ip = in + (size_t)tileRow * 4;
            #pragma unroll
            for (int i = 0; i < 4; i++) {
                int n = i * 32 + t;                    // = rlocal*4 + chunk
                float4 x = make_float4(0.f, 0.f, 0.f, 0.f);
                if (tileRow + (n >> 2) < rows) x = ip[n];
                int e0 = __float2int_rn(fmaf(x.x, qa, qb));
                int e1 = __float2int_rn(fmaf(x.y, qa, qb));
                int e2 = __float2int_rn(fmaf(x.z, qa, qb));
                int e3 = __float2int_rn(fmaf(x.w, qa, qb));
                uint32_t qw = __byte_perm(__byte_perm(e0, e1, 0x0040),
                                          __byte_perm(e2, e3, 0x0040), 0x5410);
                s_q[w][n] = qw;
                unsigned T = __dp4a(qw, 0x01010101u, 14u);   // S_c + 14, <= 74
                // K = (69*(74-T))<<16 = 0x13F20000 - T*0x00450000 (74*69=5106=0x13F2)
                s_K[w][n] = 0x13F20000u - T * 0x00450000u;
            }
            __syncwarp();

            float4* op = out + (size_t)tileRow * 8;
            #pragma unroll 2
            for (int j = 0; j < 8; j++) {
                int r = 4 * j + g;
                uint4 q = ((const uint4*)s_q[w])[r];
                uint4 K = ((const uint4*)s_K[w])[r];
                float4 ov;
                unsigned acc;
                // v = (yP+7)*0x450045 + K; lo lane 69x -> floor(x/15) at bits 10-14,
                // hi lane 69*(x+74-T) -> floor((x+74-T)/15) at bits 26-30; both
                // carry-free under mask accumulation. Bytes 1/3 of acc = Lo<<2/Hi<<2;
                // final dp4a = (FMAGIC-64) + 4*(Lo+Hi) = FMAGIC + 4*tot.
                acc  = (__dp4a(q.x, w0.x, 7u) * 0x00450045u + K.x) & 0x1C001C00u;
                acc += (__dp4a(q.y, w0.y, 7u) * 0x00450045u + K.y) & 0x1C001C00u;
                acc += (__dp4a(q.z, w0.z, 7u) * 0x00450045u + K.z) & 0x1C001C00u;
                acc += (__dp4a(q.w, w0.w, 7u) * 0x00450045u + K.w) & 0x1C001C00u;
                ov.x = fmaf(__int_as_float(__dp4a((int)acc, 0x01000100, seedC)), scale4, biasM.x);
                acc  = (__dp4a(q.x, w1.x, 7u) * 0x00450045u + K.x) & 0x1C001C00u;
                acc += (__dp4a(q.y, w1.y, 7u) * 0x00450045u + K.y) & 0x1C001C00u;
                acc += (__dp4a(q.z, w1.z, 7u) * 0x00450045u + K.z) & 0x1C001C00u;
                acc += (__dp4a(q.w, w1.w, 7u) * 0x00450045u + K.w) & 0x1C001C00u;
                ov.y = fmaf(__int_as_float(__dp4a((int)acc, 0x01000100, seedC)), scale4, biasM.y);
                acc  = (__dp4a(q.x, w2.x, 7u) * 0x00450045u + K.x) & 0x1C001C00u;
                acc += (__dp4a(q.y, w2.y, 7u) * 0x00450045u + K.y) & 0x1C001C00u;
                acc += (__dp4a(q.z, w2.z, 7u) * 0x00450045u + K.z) & 0x1C001C00u;
                acc += (__dp4a(q.w, w2.w, 7u) * 0x00450045u + K.w) & 0x1C001C00u;
                ov.z = fmaf(__int_as_float(__dp4a((int)acc, 0x01000100, seedC)), scale4, biasM.z);
                acc  = (__dp4a(q.x, w3.x, 7u) * 0x00450045u + K.x) & 0x1C001C00u;
                acc += (__dp4a(q.y, w3.y, 7u) * 0x00450045u + K.y) & 0x1C001C00u;
                acc += (__dp4a(q.z, w3.z, 7u) * 0x00450045u + K.z) & 0x1C001C00u;
                acc += (__dp4a(q.w, w3.w, 7u) * 0x00450045u + K.w) & 0x1C001C00u;
                ov.w = fmaf(__int_as_float(__dp4a((int)acc, 0x01000100, seedC)), scale4, biasM.w);
                if (tileRow + r < rows) op[(size_t)r * 8 + oq] = ov;
            }
            __syncwarp();
        }
    } else {
        // ================= SAFE PATH (some sign(w)==0) =================
        for (int tile = blockIdx.x; tile < numTiles; tile += gridDim.x) {
            int tileRow = tile * RPB + w * 32;

            const float4* ip = in + (size_t)tileRow * 4;
            #pragma unroll
            for (int i = 0; i < 4; i++) {
                int n = i * 32 + t;
                float4 x = make_float4(0.f, 0.f, 0.f, 0.f);
                if (tileRow + (n >> 2) < rows) x = ip[n];
                int e0 = __float2int_rn(fmaf(x.x, qa, qb));
                int e1 = __float2int_rn(fmaf(x.y, qa, qb));
                int e2 = __float2int_rn(fmaf(x.z, qa, qb));
                int e3 = __float2int_rn(fmaf(x.w, qa, qb));
                s_q[w][n] = __byte_perm(__byte_perm(e0, e1, 0x0040),
                                        __byte_perm(e2, e3, 0x0040), 0x5410);
            }
            __syncwarp();

            float4* op = out + (size_t)tileRow * 8;
            #pragma unroll 2
            for (int j = 0; j < 8; j++) {
                int r = 4 * j + g;
                uint4 q = ((const uint4*)s_q[w])[r];
                float4 ov;
                float* ovp = (float*)&ov;
                #pragma unroll
                for (int oi = 0; oi < 4; oi++) {
                    uint4 wp = s_wp[oq * 4 + oi];
                    uint4 wm = s_wm[oq * 4 + oi];
                    unsigned rp0 = __dp4a(q.x, wp.x, 7u), rm0 = __dp4a(q.x, wm.x, 7u);
                    unsigned rp1 = __dp4a(q.y, wp.y, 7u), rm1 = __dp4a(q.y, wm.y, 7u);
                    unsigned rp2 = __dp4a(q.z, wp.z, 7u), rm2 = __dp4a(q.z, wm.z, 7u);
                    unsigned rp3 = __dp4a(q.w, wp.w, 7u), rm3 = __dp4a(q.w, wm.w, 7u);
                    int acc = (int)__umulhi(rp0, C15) - (int)__umulhi(rm0, C15)
                            + (int)__umulhi(rp1, C15) - (int)__umulhi(rm1, C15)
                            + (int)__umulhi(rp2, C15) - (int)__umulhi(rm2, C15)
                            + (int)__umulhi(rp3, C15) - (int)__umulhi(rm3, C15);
                    ovp[oi] = fmaf((float)acc, scale, ((const float*)&bias)[oi]);
                }
                if (tileRow + r < rows) op[(size_t)r * 8 + oq] = ov;
            }
            __syncwarp();
        }
    }
}

extern "C" void kernel_launch(void* const* d_in, const int* in_sizes, int n_in,
                              void* d_out, int out_size) {
    const float* Input  = (const float*)d_in[0];
    const float* weight = (const float*)d_in[1];
    const float* InMin  = (const float*)d_in[2];
    const float* InMax  = (const float*)d_in[3];
    float* out = (float*)d_out;

    int rows = in_sizes[0] / IN_DIM;
    int numTiles = (rows + RPB - 1) / RPB;

    int blocks = 148 * 4;                  // one resident wave at 4 CTAs/SM
    if (blocks > numTiles) blocks = numTiles;

    quant_fused_kernel<<<blocks, TPB>>>((const float4*)Input, (float4*)out,
                                        weight, InMin, InMax, rows, numTiles);
}